// round 3
// baseline (speedup 1.0000x reference)
#include <cuda_runtime.h>
#include <math.h>

#define NN 50000            // nodes
#define NE 800000           // edges
#define NG 512              // graphs
#define DD 128              // node hidden
#define MM 256              // message hidden
#define TT 4                // edge types
#define NPASS 4
#define GH 256              // graph hidden

// ---------------- scratch (static __device__, no allocations) ----------------
__device__ float g_h[NN * DD];
__device__ float g_preagg[NN * (TT * DD)];    // (N, 512) node-major [t0|t1|t2|t3]
__device__ int   g_counts[NN * TT];
__device__ float g_msgs[NN * MM];
__device__ float g_gi[NN * 3 * DD];
__device__ float g_gh[NN * 3 * DD];
__device__ float g_attn[NN];
__device__ int   g_hist[NN];
__device__ int   g_cursor[NN];
__device__ int   g_off[NN + 1];
__device__ int   g_part[256];
__device__ int2  g_csr[NE];                   // (dst, type) sorted by src

#define NB_SCAN ((NN + 255) / 256)            // 196

// ---------------- setup kernels ----------------
__global__ void k_zero2(int* a, int* b, int n) {
    int i = blockIdx.x * blockDim.x + threadIdx.x;
    if (i < n) { a[i] = 0; b[i] = 0; }
}

__global__ void k_hist(const int* __restrict__ src, int* __restrict__ hist) {
    int i = blockIdx.x * blockDim.x + threadIdx.x;
    if (i < NE) atomicAdd(&hist[src[i]], 1);
}

// 3-phase scan: block-local exclusive + partials
__global__ void k_scan1(const int* __restrict__ hist, int* __restrict__ off,
                        int* __restrict__ part) {
    __shared__ int sh[256];
    int t = threadIdx.x, i = blockIdx.x * 256 + t;
    int v = (i < NN) ? hist[i] : 0;
    sh[t] = v;
    __syncthreads();
#pragma unroll
    for (int o = 1; o < 256; o <<= 1) {
        int x = (t >= o) ? sh[t - o] : 0;
        __syncthreads();
        sh[t] += x;
        __syncthreads();
    }
    if (i < NN) off[i] = sh[t] - v;
    if (t == 255) part[blockIdx.x] = sh[255];
}

__global__ void k_scan2(int* __restrict__ part, int nb) {
    __shared__ int sh[256];
    int t = threadIdx.x;
    int v = (t < nb) ? part[t] : 0;
    sh[t] = v;
    __syncthreads();
#pragma unroll
    for (int o = 1; o < 256; o <<= 1) {
        int x = (t >= o) ? sh[t - o] : 0;
        __syncthreads();
        sh[t] += x;
        __syncthreads();
    }
    if (t < nb) part[t] = sh[t] - v;
}

__global__ void k_scan3(const int* __restrict__ part, int* __restrict__ off) {
    int i = blockIdx.x * 256 + threadIdx.x;
    if (i < NN) off[i] += part[blockIdx.x];
    if (i == 0) off[NN] = NE;
}

__global__ void k_scatter(const int* __restrict__ src, const int* __restrict__ dst,
                          const int* __restrict__ typ,
                          const int* __restrict__ off, int* __restrict__ cursor,
                          int2* __restrict__ csr) {
    int i = blockIdx.x * blockDim.x + threadIdx.x;
    if (i >= NE) return;
    int s = src[i];
    int pos = off[s] + atomicAdd(&cursor[s], 1);
    csr[pos] = make_int2(dst[i], typ[i]);
}

__global__ void k_embed(const int* __restrict__ nt, const float* __restrict__ emb,
                        float* __restrict__ h) {
    int t = blockIdx.x * blockDim.x + threadIdx.x;
    if (t >= NN * 32) return;
    int node = t >> 5, c = t & 31;
    reinterpret_cast<float4*>(h)[t] =
        reinterpret_cast<const float4*>(emb)[nt[node] * 32 + c];
}

// ---------------- per-pass: CSR aggregation (warp per node, 4x edge unroll) ----
__device__ __forceinline__ void agg_one(float4 a[4], float c[4],
                                        const float4& v, int ty) {
#pragma unroll
    for (int t = 0; t < 4; t++) {
        float m = (ty == t) ? 1.f : 0.f;
        a[t].x = fmaf(v.x, m, a[t].x);
        a[t].y = fmaf(v.y, m, a[t].y);
        a[t].z = fmaf(v.z, m, a[t].z);
        a[t].w = fmaf(v.w, m, a[t].w);
        c[t] += m;
    }
}

__global__ void k_agg(const float* __restrict__ h, const int* __restrict__ off,
                      const int2* __restrict__ csr,
                      float* __restrict__ preagg, int* __restrict__ counts) {
    int warp = (blockIdx.x * blockDim.x + threadIdx.x) >> 5;
    int lane = threadIdx.x & 31;
    if (warp >= NN) return;
    int beg = off[warp], end = off[warp + 1];
    float4 a[4];
    float c[4] = {0, 0, 0, 0};
#pragma unroll
    for (int t = 0; t < 4; t++) a[t] = make_float4(0, 0, 0, 0);
    const float4* h4 = reinterpret_cast<const float4*>(h);
    int e = beg;
    for (; e + 4 <= end; e += 4) {
        int2 d0 = csr[e], d1 = csr[e + 1], d2 = csr[e + 2], d3 = csr[e + 3];
        float4 v0 = h4[d0.x * 32 + lane];
        float4 v1 = h4[d1.x * 32 + lane];
        float4 v2 = h4[d2.x * 32 + lane];
        float4 v3 = h4[d3.x * 32 + lane];
        agg_one(a, c, v0, d0.y);
        agg_one(a, c, v1, d1.y);
        agg_one(a, c, v2, d2.y);
        agg_one(a, c, v3, d3.y);
    }
    for (; e < end; e++) {
        int2 d = csr[e];
        float4 v = h4[d.x * 32 + lane];
        agg_one(a, c, v, d.y);
    }
    float4* p4 = reinterpret_cast<float4*>(preagg);
    int base = warp * 128;
#pragma unroll
    for (int t = 0; t < 4; t++) p4[base + t * 32 + lane] = a[t];
    if (lane == 0) {
#pragma unroll
        for (int t = 0; t < 4; t++) counts[warp * 4 + t] = (int)c[t];
    }
}

// ---------------- TF32 tensor-core GEMM, fragment-order smem, double-buffered --
// MODE 0: C = acc + bias[col]
// MODE 1: C = relu(acc + sum_t counts[r][t]*bmsg[t*MM+col])
// MODE 2: atomicAdd(gout[n2g[r]*GH+col], attn[r]*(acc+bias[col]))

__device__ __forceinline__ unsigned f2tf(float x) {
    unsigned r;
    asm("cvt.rna.tf32.f32 %0, %1;" : "=r"(r) : "f"(x));
    return r;
}

__device__ __forceinline__ void mma_tf32(float* c, unsigned a0, unsigned a1,
                                         unsigned a2, unsigned a3,
                                         unsigned b0, unsigned b1) {
    asm volatile(
        "mma.sync.aligned.m16n8k8.row.col.f32.tf32.tf32.f32 "
        "{%0,%1,%2,%3}, {%4,%5,%6,%7}, {%8,%9}, {%0,%1,%2,%3};"
        : "+f"(c[0]), "+f"(c[1]), "+f"(c[2]), "+f"(c[3])
        : "r"(a0), "r"(a1), "r"(a2), "r"(a3), "r"(b0), "r"(b1));
}

// frag-order smem word indices (within 8192-word half per buffer pair)
// A: [buf][wmq 4][mt 2][kk 4][lane 32][e 4]
#define AF_IDX(buf, wmq, mt, kk, lane, e) \
    (((((((buf) * 4 + (wmq)) * 2 + (mt)) * 4 + (kk)) * 32 + (lane)) * 4) + (e))
// B: [buf][wnq 2][kk 4][ntp 4][lane 32][e 4]
#define BF_IDX(buf, wnq, kk, ntp, lane, e) \
    (((((((buf) * 2 + (wnq)) * 4 + (kk)) * 4 + (ntp)) * 32 + (lane)) * 4) + (e))

template <int MODE, bool TRANSB>
__global__ void __launch_bounds__(256)
k_mma(const float* __restrict__ A, const float* __restrict__ B,
      float* __restrict__ C, int Nrows, int K, int Ncols,
      const float* __restrict__ bias,
      const int* __restrict__ counts, const float* __restrict__ bmsg,
      const float* __restrict__ attn, const int* __restrict__ n2g,
      float* __restrict__ gout) {
    extern __shared__ unsigned sm[];          // [0,8192): Af, [8192,16384): Bf
    unsigned* Af = sm;
    unsigned* Bf = sm + 8192;

    const int tid = threadIdx.x;
    const int lane = tid & 31;
    const int warp = tid >> 5;
    const int rowBase = blockIdx.x * 128;
    const int colBase = blockIdx.y * 128;
    const int wmq = warp & 3;                 // A quadrant (M/32)
    const int wnq = warp >> 2;                // B half (N/64)
    const int wm = wmq * 32;
    const int wn = wnq * 64;
    const int qrow = lane >> 2;
    const int qcol = lane & 3;

    float acc[2][8][4];
#pragma unroll
    for (int mt = 0; mt < 2; mt++)
#pragma unroll
        for (int nt = 0; nt < 8; nt++)
#pragma unroll
            for (int q = 0; q < 4; q++) acc[mt][nt][q] = 0.f;

    // ---- staging regs + index precompute ----
    float4 aR[4], bR[4];
    const int aRow0 = tid >> 3;               // 0..31
    const int aC0 = (tid & 7) * 4;            // 0..28
    const int a_kk = aC0 >> 3;
    const int a_sel = (aC0 >> 2) & 1;
    const int a_mt = (aRow0 >> 4) & 1;
    const int a_half = (aRow0 >> 3) & 1;
    const int a_qrow = aRow0 & 7;
    // B non-trans
    const int bK = tid >> 3;                  // 0..31
    const int b_kk = bK >> 3;
    const int b_sel = (bK >> 2) & 1;
    const int b_qc = bK & 3;
    // B trans
    const int btN = tid >> 1;                 // 0..127
    const int btKb = (tid & 1) * 16;
    const int bt_wnq = btN >> 6;
    const int bt_nt = (btN >> 3) & 7;
    const int bt_ntp = bt_nt >> 1;
    const int bt_u = bt_nt & 1;
    const int bt_qr = btN & 7;

    auto loadA = [&](int k0) {
#pragma unroll
        for (int i = 0; i < 4; i++) {
            int row = aRow0 + 32 * i;
            if (rowBase + row < Nrows)
                aR[i] = *reinterpret_cast<const float4*>(
                    A + (size_t)(rowBase + row) * K + k0 + aC0);
            else
                aR[i] = make_float4(0, 0, 0, 0);
        }
    };
    auto loadB = [&](int k0) {
        if (!TRANSB) {
#pragma unroll
            for (int i = 0; i < 4; i++) {
                int n = ((tid & 7) + 8 * i) * 4;
                bR[i] = *reinterpret_cast<const float4*>(
                    B + (size_t)(k0 + bK) * Ncols + colBase + n);
            }
        } else {
#pragma unroll
            for (int i = 0; i < 4; i++) {
                int k4 = btKb + 4 * i;
                bR[i] = *reinterpret_cast<const float4*>(
                    B + (size_t)(colBase + btN) * K + k0 + k4);
            }
        }
    };
    auto storeS = [&](int buf) {
#pragma unroll
        for (int i = 0; i < 4; i++) {         // wmq = i
            int e = a_sel * 2 + a_half;
            unsigned* p = &Af[AF_IDX(buf, i, a_mt, a_kk, a_qrow * 4, e)];
            p[0]  = f2tf(aR[i].x);
            p[4]  = f2tf(aR[i].y);
            p[8]  = f2tf(aR[i].z);
            p[12] = f2tf(aR[i].w);
        }
        if (!TRANSB) {
#pragma unroll
            for (int i = 0; i < 4; i++) {
                int n = ((tid & 7) + 8 * i) * 4;
                int wq = n >> 6;
                int nt = (n >> 3) & 7;
                int e = (nt & 1) * 2 + b_sel;
                int l0 = (n & 7) * 4 + b_qc;  // qrow grows with q by +4 lanes
                unsigned* p = &Bf[BF_IDX(buf, wq, b_kk, nt >> 1, l0, e)];
                p[0]  = f2tf(bR[i].x);
                p[16] = f2tf(bR[i].y);        // +4 lanes = +16 words
                p[32] = f2tf(bR[i].z);
                p[48] = f2tf(bR[i].w);
            }
        } else {
#pragma unroll
            for (int i = 0; i < 4; i++) {
                int k4 = btKb + 4 * i;
                int kk = k4 >> 3;
                int sel = (k4 >> 2) & 1;
                int e = bt_u * 2 + sel;
                unsigned* p = &Bf[BF_IDX(buf, bt_wnq, kk, bt_ntp, bt_qr * 4, e)];
                p[0]  = f2tf(bR[i].x);        // qcol grows with q by +1 lane? no:
                p[4]  = f2tf(bR[i].y);        // lane = qr*4 + qcol, qcol=q -> +4 words
                p[8]  = f2tf(bR[i].z);
                p[12] = f2tf(bR[i].w);
            }
        }
    };

    const int nT = K / 32;
    loadA(0);
    loadB(0);
    storeS(0);
    __syncthreads();
    for (int t = 0; t < nT; t++) {
        int buf = t & 1;
        if (t + 1 < nT) { loadA((t + 1) * 32); loadB((t + 1) * 32); }
#pragma unroll
        for (int kk = 0; kk < 4; kk++) {
            uint4 av0 = *reinterpret_cast<const uint4*>(&Af[AF_IDX(buf, wmq, 0, kk, lane, 0)]);
            uint4 av1 = *reinterpret_cast<const uint4*>(&Af[AF_IDX(buf, wmq, 1, kk, lane, 0)]);
#pragma unroll
            for (int ntp = 0; ntp < 4; ntp++) {
                uint4 bv = *reinterpret_cast<const uint4*>(&Bf[BF_IDX(buf, wnq, kk, ntp, lane, 0)]);
                mma_tf32(acc[0][2 * ntp],     av0.x, av0.y, av0.z, av0.w, bv.x, bv.y);
                mma_tf32(acc[1][2 * ntp],     av1.x, av1.y, av1.z, av1.w, bv.x, bv.y);
                mma_tf32(acc[0][2 * ntp + 1], av0.x, av0.y, av0.z, av0.w, bv.z, bv.w);
                mma_tf32(acc[1][2 * ntp + 1], av1.x, av1.y, av1.z, av1.w, bv.z, bv.w);
            }
        }
        if (t + 1 < nT) storeS((t + 1) & 1);
        __syncthreads();
    }

    // epilogue: c0:(qrow,2qcol) c1:(qrow,2qcol+1) c2/c3:(qrow+8,..)
#pragma unroll
    for (int mt = 0; mt < 2; mt++) {
#pragma unroll
        for (int half = 0; half < 2; half++) {
            int r = rowBase + wm + mt * 16 + qrow + half * 8;
            if (r >= Nrows) continue;
            float ct0 = 0, ct1 = 0, ct2 = 0, ct3 = 0, at = 0;
            int gidx = 0;
            if (MODE == 1) {
                ct0 = (float)counts[r * 4 + 0]; ct1 = (float)counts[r * 4 + 1];
                ct2 = (float)counts[r * 4 + 2]; ct3 = (float)counts[r * 4 + 3];
            } else if (MODE == 2) {
                at = attn[r];
                gidx = n2g[r];
            }
#pragma unroll
            for (int nt = 0; nt < 8; nt++) {
#pragma unroll
                for (int e = 0; e < 2; e++) {
                    int c = colBase + wn + nt * 8 + 2 * qcol + e;
                    float v = acc[mt][nt][half * 2 + e];
                    if (MODE == 1) {
                        v += ct0 * bmsg[c] + ct1 * bmsg[MM + c] +
                             ct2 * bmsg[2 * MM + c] + ct3 * bmsg[3 * MM + c];
                        C[(size_t)r * Ncols + c] = fmaxf(v, 0.f);
                    } else if (MODE == 0) {
                        C[(size_t)r * Ncols + c] = v + bias[c];
                    } else {
                        atomicAdd(&gout[(size_t)gidx * GH + c], at * (v + bias[c]));
                    }
                }
            }
        }
    }
}

// ---------------- GRU gates (elementwise) ----------------
__global__ void k_gates(const float* __restrict__ gi, const float* __restrict__ gh,
                        float* __restrict__ h) {
    int i = blockIdx.x * blockDim.x + threadIdx.x;
    if (i >= NN * DD) return;
    int n = i >> 7, j = i & 127;
    const float* gin = gi + (size_t)n * 3 * DD;
    const float* ghn = gh + (size_t)n * 3 * DD;
    float r = 1.f / (1.f + expf(-(gin[j] + ghn[j])));
    float z = 1.f / (1.f + expf(-(gin[DD + j] + ghn[DD + j])));
    float nn = tanhf(gin[2 * DD + j] + r * ghn[2 * DD + j]);
    h[i] = (1.f - z) * nn + z * h[i];
}

// ---------------- readout attn (warp per node) ----------------
__global__ void k_attn(const float* __restrict__ h, const float* __restrict__ wg,
                       const float* __restrict__ bg, float* __restrict__ attn) {
    int warp = (blockIdx.x * blockDim.x + threadIdx.x) >> 5;
    int lane = threadIdx.x & 31;
    if (warp >= NN) return;
    const float4* h4 = reinterpret_cast<const float4*>(h + (size_t)warp * DD);
    const float4* w4 = reinterpret_cast<const float4*>(wg);
    float4 a = h4[lane], b = w4[lane];
    float s = a.x * b.x + a.y * b.y + a.z * b.z + a.w * b.w;
#pragma unroll
    for (int o = 16; o; o >>= 1) s += __shfl_xor_sync(0xFFFFFFFFu, s, o);
    if (lane == 0) attn[warp] = 1.f / (1.f + expf(-(s + bg[0])));
}

// ---------------- launch ----------------
static inline void* symaddr(const void* sym) {
    void* p = nullptr;
    cudaGetSymbolAddress(&p, sym);
    return p;
}

extern "C" void kernel_launch(void* const* d_in, const int* in_sizes, int n_in,
                              void* d_out, int out_size) {
    const int*   node_types = (const int*)d_in[0];
    const int*   edge_src   = (const int*)d_in[1];
    const int*   edge_dst   = (const int*)d_in[2];
    const int*   edge_type  = (const int*)d_in[3];
    const int*   node2graph = (const int*)d_in[4];
    const float* emb   = (const float*)d_in[5];
    const float* W_msg = (const float*)d_in[6];
    const float* b_msg = (const float*)d_in[7];
    const float* W_ih  = (const float*)d_in[8];
    const float* W_hh  = (const float*)d_in[9];
    const float* b_ih  = (const float*)d_in[10];
    const float* b_hh  = (const float*)d_in[11];
    const float* w_gate= (const float*)d_in[12];
    const float* b_gate= (const float*)d_in[13];
    const float* W_g   = (const float*)d_in[14];
    const float* b_g   = (const float*)d_in[15];
    float* out = (float*)d_out;

    float* h      = (float*)symaddr(g_h);
    float* preagg = (float*)symaddr(g_preagg);
    int*   counts = (int*)  symaddr(g_counts);
    float* msgs   = (float*)symaddr(g_msgs);
    float* gi     = (float*)symaddr(g_gi);
    float* gh     = (float*)symaddr(g_gh);
    float* attn   = (float*)symaddr(g_attn);
    int*   hist   = (int*)  symaddr(g_hist);
    int*   cursor = (int*)  symaddr(g_cursor);
    int*   off    = (int*)  symaddr(g_off);
    int*   part   = (int*)  symaddr(g_part);
    int2*  csr    = (int2*) symaddr(g_csr);

    const int SMEM = 16384 * sizeof(unsigned);   // 64 KB dynamic
    cudaFuncSetAttribute(k_mma<1, false>, cudaFuncAttributeMaxDynamicSharedMemorySize, SMEM);
    cudaFuncSetAttribute(k_mma<0, true>,  cudaFuncAttributeMaxDynamicSharedMemorySize, SMEM);
    cudaFuncSetAttribute(k_mma<2, false>, cudaFuncAttributeMaxDynamicSharedMemorySize, SMEM);

    // --- build CSR by src ---
    k_zero2<<<(NN + 255) / 256, 256>>>(hist, cursor, NN);
    k_hist<<<(NE + 255) / 256, 256>>>(edge_src, hist);
    k_scan1<<<NB_SCAN, 256>>>(hist, off, part);
    k_scan2<<<1, 256>>>(part, NB_SCAN);
    k_scan3<<<NB_SCAN, 256>>>(part, off);
    k_scatter<<<(NE + 255) / 256, 256>>>(edge_src, edge_dst, edge_type, off, cursor, csr);

    // --- init h = emb_table[node_types] ---
    k_embed<<<(NN * 32 + 255) / 256, 256>>>(node_types, emb, h);

    const int rowBlocks = (NN + 127) / 128;  // 391

    for (int p = 0; p < NPASS; p++) {
        k_agg<<<(NN * 32 + 255) / 256, 256>>>(h, off, csr, preagg, counts);
        {   // msgs = relu(pre_agg @ W_msg_cat + counts . b_msg)
            dim3 g(rowBlocks, MM / 128);
            k_mma<1, false><<<g, 256, SMEM>>>(preagg, W_msg, msgs, NN, TT * DD, MM,
                                              nullptr, counts, b_msg, nullptr, nullptr, nullptr);
        }
        {   // gi = msgs @ W_ih^T + b_ih
            dim3 g(rowBlocks, (3 * DD) / 128);
            k_mma<0, true><<<g, 256, SMEM>>>(msgs, W_ih, gi, NN, MM, 3 * DD,
                                             b_ih, nullptr, nullptr, nullptr, nullptr, nullptr);
        }
        {   // gh = h @ W_hh^T + b_hh
            dim3 g(rowBlocks, (3 * DD) / 128);
            k_mma<0, true><<<g, 256, SMEM>>>(h, W_hh, gh, NN, DD, 3 * DD,
                                             b_hh, nullptr, nullptr, nullptr, nullptr, nullptr);
        }
        k_gates<<<(NN * DD + 255) / 256, 256>>>(gi, gh, h);
    }

    // --- output: h first, then gated graph readout ---
    cudaMemcpyAsync(out, h, (size_t)NN * DD * sizeof(float),
                    cudaMemcpyDeviceToDevice);
    float* gout = out + ((size_t)out_size - (size_t)NG * GH);
    cudaMemsetAsync(gout, 0, (size_t)NG * GH * sizeof(float));

    k_attn<<<(NN * 32 + 255) / 256, 256>>>(h, w_gate, b_gate, attn);
    {
        dim3 g(rowBlocks, GH / 128);
        k_mma<2, false><<<g, 256, SMEM>>>(h, W_g, nullptr, NN, DD, GH,
                                          b_g, nullptr, nullptr, attn, node2graph, gout);
    }
}

// round 4
// speedup vs baseline: 1.4457x; 1.4457x over previous
#include <cuda_runtime.h>
#include <math.h>

#define NN 50000            // nodes
#define NE 800000           // edges
#define NG 512              // graphs
#define DD 128              // node hidden
#define MM 256              // message hidden
#define TT 4                // edge types
#define NPASS 4
#define GH 256              // graph hidden

// ---------------- scratch (static __device__, no allocations) ----------------
__device__ float g_h[NN * DD];
__device__ float g_preagg[NN * (TT * DD)];    // (N, 512) node-major [t0|t1|t2|t3]
__device__ int   g_counts[NN * TT];
__device__ float g_msgs[NN * MM];
__device__ float g_gi[NN * 3 * DD];
__device__ float g_gh[NN * 3 * DD];
__device__ float g_attn[NN];
__device__ int   g_hist[NN];
__device__ int   g_cursor[NN];
__device__ int   g_off[NN + 1];
__device__ int   g_part[256];
__device__ int2  g_csr[NE];                   // (dst, type) sorted by src

#define NB_SCAN ((NN + 255) / 256)            // 196

// ---------------- setup kernels ----------------
__global__ void k_zero2(int* a, int* b, int n) {
    int i = blockIdx.x * blockDim.x + threadIdx.x;
    if (i < n) { a[i] = 0; b[i] = 0; }
}

__global__ void k_hist(const int* __restrict__ src, int* __restrict__ hist) {
    int i = blockIdx.x * blockDim.x + threadIdx.x;
    if (i < NE) atomicAdd(&hist[src[i]], 1);
}

// 3-phase scan
__global__ void k_scan1(const int* __restrict__ hist, int* __restrict__ off,
                        int* __restrict__ part) {
    __shared__ int sh[256];
    int t = threadIdx.x, i = blockIdx.x * 256 + t;
    int v = (i < NN) ? hist[i] : 0;
    sh[t] = v;
    __syncthreads();
#pragma unroll
    for (int o = 1; o < 256; o <<= 1) {
        int x = (t >= o) ? sh[t - o] : 0;
        __syncthreads();
        sh[t] += x;
        __syncthreads();
    }
    if (i < NN) off[i] = sh[t] - v;
    if (t == 255) part[blockIdx.x] = sh[255];
}

__global__ void k_scan2(int* __restrict__ part, int nb) {
    __shared__ int sh[256];
    int t = threadIdx.x;
    int v = (t < nb) ? part[t] : 0;
    sh[t] = v;
    __syncthreads();
#pragma unroll
    for (int o = 1; o < 256; o <<= 1) {
        int x = (t >= o) ? sh[t - o] : 0;
        __syncthreads();
        sh[t] += x;
        __syncthreads();
    }
    if (t < nb) part[t] = sh[t] - v;
}

__global__ void k_scan3(const int* __restrict__ part, int* __restrict__ off) {
    int i = blockIdx.x * 256 + threadIdx.x;
    if (i < NN) off[i] += part[blockIdx.x];
    if (i == 0) off[NN] = NE;
}

__global__ void k_scatter(const int* __restrict__ src, const int* __restrict__ dst,
                          const int* __restrict__ typ,
                          const int* __restrict__ off, int* __restrict__ cursor,
                          int2* __restrict__ csr) {
    int i = blockIdx.x * blockDim.x + threadIdx.x;
    if (i >= NE) return;
    int s = src[i];
    int pos = off[s] + atomicAdd(&cursor[s], 1);
    csr[pos] = make_int2(dst[i], typ[i]);
}

__global__ void k_embed(const int* __restrict__ nt, const float* __restrict__ emb,
                        float* __restrict__ h) {
    int t = blockIdx.x * blockDim.x + threadIdx.x;
    if (t >= NN * 32) return;
    int node = t >> 5, c = t & 31;
    reinterpret_cast<float4*>(h)[t] =
        reinterpret_cast<const float4*>(emb)[nt[node] * 32 + c];
}

// ---------------- per-pass: CSR aggregation (warp per node, 4x edge unroll) ----
__device__ __forceinline__ void agg_one(float4 a[4], float c[4],
                                        const float4& v, int ty) {
#pragma unroll
    for (int t = 0; t < 4; t++) {
        float m = (ty == t) ? 1.f : 0.f;
        a[t].x = fmaf(v.x, m, a[t].x);
        a[t].y = fmaf(v.y, m, a[t].y);
        a[t].z = fmaf(v.z, m, a[t].z);
        a[t].w = fmaf(v.w, m, a[t].w);
        c[t] += m;
    }
}

__global__ void k_agg(const float* __restrict__ h, const int* __restrict__ off,
                      const int2* __restrict__ csr,
                      float* __restrict__ preagg, int* __restrict__ counts) {
    int warp = (blockIdx.x * blockDim.x + threadIdx.x) >> 5;
    int lane = threadIdx.x & 31;
    if (warp >= NN) return;
    int beg = off[warp], end = off[warp + 1];
    float4 a[4];
    float c[4] = {0, 0, 0, 0};
#pragma unroll
    for (int t = 0; t < 4; t++) a[t] = make_float4(0, 0, 0, 0);
    const float4* h4 = reinterpret_cast<const float4*>(h);
    int e = beg;
    for (; e + 4 <= end; e += 4) {
        int2 d0 = csr[e], d1 = csr[e + 1], d2 = csr[e + 2], d3 = csr[e + 3];
        float4 v0 = h4[d0.x * 32 + lane];
        float4 v1 = h4[d1.x * 32 + lane];
        float4 v2 = h4[d2.x * 32 + lane];
        float4 v3 = h4[d3.x * 32 + lane];
        agg_one(a, c, v0, d0.y);
        agg_one(a, c, v1, d1.y);
        agg_one(a, c, v2, d2.y);
        agg_one(a, c, v3, d3.y);
    }
    for (; e < end; e++) {
        int2 d = csr[e];
        float4 v = h4[d.x * 32 + lane];
        agg_one(a, c, v, d.y);
    }
    float4* p4 = reinterpret_cast<float4*>(preagg);
    int base = warp * 128;
#pragma unroll
    for (int t = 0; t < 4; t++) p4[base + t * 32 + lane] = a[t];
    if (lane == 0) {
#pragma unroll
        for (int t = 0; t < 4; t++) counts[warp * 4 + t] = (int)c[t];
    }
}

// ---------------- TF32 tensor-core GEMM 128x128x32 (R2 known-good) ------------
// MODE 0: C = acc + bias[col]
// MODE 1: C = relu(acc + sum_t counts[r][t]*bmsg[t*MM+col])
// MODE 2: atomicAdd(gout[n2g[r]*GH+col], attn[r]*(acc+bias[col]))

__device__ __forceinline__ unsigned f2tf(float x) {
    unsigned r;
    asm("cvt.rna.tf32.f32 %0, %1;" : "=r"(r) : "f"(x));
    return r;
}

__device__ __forceinline__ void mma_tf32(float* c, const unsigned* a, const unsigned* b) {
    asm volatile(
        "mma.sync.aligned.m16n8k8.row.col.f32.tf32.tf32.f32 "
        "{%0,%1,%2,%3}, {%4,%5,%6,%7}, {%8,%9}, {%0,%1,%2,%3};"
        : "+f"(c[0]), "+f"(c[1]), "+f"(c[2]), "+f"(c[3])
        : "r"(a[0]), "r"(a[1]), "r"(a[2]), "r"(a[3]), "r"(b[0]), "r"(b[1]));
}

template <int MODE, bool TRANSB>
__global__ void __launch_bounds__(256)
k_mma(const float* __restrict__ A, const float* __restrict__ B,
      float* __restrict__ C, int Nrows, int K, int Ncols,
      const float* __restrict__ bias,
      const int* __restrict__ counts, const float* __restrict__ bmsg,
      const float* __restrict__ attn, const int* __restrict__ n2g,
      float* __restrict__ gout) {
    constexpr int BM = 128, BN = 128, BK = 32;
    constexpr int SA = 36, SB = 136;            // conflict-free strides
    __shared__ unsigned As[BM][SA];             // [m][k]
    __shared__ unsigned Bs[BK][SB];             // [k][n]

    const int tid = threadIdx.x;
    const int lane = tid & 31;
    const int warp = tid >> 5;
    const int rowBase = blockIdx.x * BM;
    const int colBase = blockIdx.y * BN;
    const int wm = (warp & 3) * 32;             // warp M offset
    const int wn = (warp >> 2) * 64;            // warp N offset
    const int qrow = lane >> 2;                 // 0..7
    const int qcol = lane & 3;                  // 0..3

    float acc[2][8][4];
#pragma unroll
    for (int mt = 0; mt < 2; mt++)
#pragma unroll
        for (int nt = 0; nt < 8; nt++)
#pragma unroll
            for (int q = 0; q < 4; q++) acc[mt][nt][q] = 0.f;

    float4 aR[4];
    float4 bR[4];
    const int aRow0 = tid >> 3;                 // 0..31 (stride 32, 4 iters)
    const int aCol = (tid & 7) * 4;             // 0..28
    const int bnRow = tid >> 3;                 // non-trans: k = tid/8
    const int btN = tid >> 1;                   // trans: n = tid/2
    const int btK = (tid & 1) * 16;             // trans: k segment

    auto loadA = [&](int k0) {
#pragma unroll
        for (int i = 0; i < 4; i++) {
            int row = aRow0 + 32 * i;
            if (rowBase + row < Nrows)
                aR[i] = *reinterpret_cast<const float4*>(
                    A + (size_t)(rowBase + row) * K + k0 + aCol);
            else
                aR[i] = make_float4(0, 0, 0, 0);
        }
    };
    auto loadB = [&](int k0) {
        if (!TRANSB) {
#pragma unroll
            for (int i = 0; i < 4; i++) {
                int n = ((tid & 7) + 8 * i) * 4;
                bR[i] = *reinterpret_cast<const float4*>(
                    B + (size_t)(k0 + bnRow) * Ncols + colBase + n);
            }
        } else {
#pragma unroll
            for (int i = 0; i < 4; i++) {
                int k4 = btK + 4 * i;
                bR[i] = *reinterpret_cast<const float4*>(
                    B + (size_t)(colBase + btN) * K + k0 + k4);
            }
        }
    };
    auto storeS = [&]() {
#pragma unroll
        for (int i = 0; i < 4; i++) {
            int row = aRow0 + 32 * i;
            As[row][aCol + 0] = f2tf(aR[i].x);
            As[row][aCol + 1] = f2tf(aR[i].y);
            As[row][aCol + 2] = f2tf(aR[i].z);
            As[row][aCol + 3] = f2tf(aR[i].w);
        }
        if (!TRANSB) {
#pragma unroll
            for (int i = 0; i < 4; i++) {
                int n = ((tid & 7) + 8 * i) * 4;
                Bs[bnRow][n + 0] = f2tf(bR[i].x);
                Bs[bnRow][n + 1] = f2tf(bR[i].y);
                Bs[bnRow][n + 2] = f2tf(bR[i].z);
                Bs[bnRow][n + 3] = f2tf(bR[i].w);
            }
        } else {
#pragma unroll
            for (int i = 0; i < 4; i++) {
                int k4 = btK + 4 * i;
                Bs[k4 + 0][btN] = f2tf(bR[i].x);
                Bs[k4 + 1][btN] = f2tf(bR[i].y);
                Bs[k4 + 2][btN] = f2tf(bR[i].z);
                Bs[k4 + 3][btN] = f2tf(bR[i].w);
            }
        }
    };

    loadA(0);
    loadB(0);
    for (int k0 = 0; k0 < K; k0 += BK) {
        storeS();
        __syncthreads();
        if (k0 + BK < K) { loadA(k0 + BK); loadB(k0 + BK); }
#pragma unroll
        for (int kk = 0; kk < BK / 8; kk++) {
            unsigned af[2][4];
#pragma unroll
            for (int mt = 0; mt < 2; mt++) {
                af[mt][0] = As[wm + mt * 16 + qrow][kk * 8 + qcol];
                af[mt][1] = As[wm + mt * 16 + qrow + 8][kk * 8 + qcol];
                af[mt][2] = As[wm + mt * 16 + qrow][kk * 8 + qcol + 4];
                af[mt][3] = As[wm + mt * 16 + qrow + 8][kk * 8 + qcol + 4];
            }
            unsigned bf[8][2];
#pragma unroll
            for (int nt = 0; nt < 8; nt++) {
                bf[nt][0] = Bs[kk * 8 + qcol][wn + nt * 8 + qrow];
                bf[nt][1] = Bs[kk * 8 + qcol + 4][wn + nt * 8 + qrow];
            }
#pragma unroll
            for (int mt = 0; mt < 2; mt++)
#pragma unroll
                for (int nt = 0; nt < 8; nt++)
                    mma_tf32(acc[mt][nt], af[mt], bf[nt]);
        }
        __syncthreads();
    }

#pragma unroll
    for (int mt = 0; mt < 2; mt++) {
#pragma unroll
        for (int half = 0; half < 2; half++) {
            int r = rowBase + wm + mt * 16 + qrow + half * 8;
            if (r >= Nrows) continue;
            float ct0 = 0, ct1 = 0, ct2 = 0, ct3 = 0, at = 0;
            int gidx = 0;
            if (MODE == 1) {
                ct0 = (float)counts[r * 4 + 0]; ct1 = (float)counts[r * 4 + 1];
                ct2 = (float)counts[r * 4 + 2]; ct3 = (float)counts[r * 4 + 3];
            } else if (MODE == 2) {
                at = attn[r];
                gidx = n2g[r];
            }
#pragma unroll
            for (int nt = 0; nt < 8; nt++) {
#pragma unroll
                for (int e = 0; e < 2; e++) {
                    int c = colBase + wn + nt * 8 + 2 * qcol + e;
                    float v = acc[mt][nt][half * 2 + e];
                    if (MODE == 1) {
                        v += ct0 * bmsg[c] + ct1 * bmsg[MM + c] +
                             ct2 * bmsg[2 * MM + c] + ct3 * bmsg[3 * MM + c];
                        C[(size_t)r * Ncols + c] = fmaxf(v, 0.f);
                    } else if (MODE == 0) {
                        C[(size_t)r * Ncols + c] = v + bias[c];
                    } else {
                        atomicAdd(&gout[(size_t)gidx * GH + c], at * (v + bias[c]));
                    }
                }
            }
        }
    }
}

// ---------------- GRU gates (float4 vectorized) ----------------
__device__ __forceinline__ float4 sig4(float4 x) {
    return make_float4(1.f / (1.f + __expf(-x.x)), 1.f / (1.f + __expf(-x.y)),
                       1.f / (1.f + __expf(-x.z)), 1.f / (1.f + __expf(-x.w)));
}

__global__ void k_gates(const float* __restrict__ gi, const float* __restrict__ gh,
                        float* __restrict__ h) {
    int i = blockIdx.x * blockDim.x + threadIdx.x;   // one float4 per thread
    if (i >= NN * DD / 4) return;
    int n = i >> 5, j = i & 31;                      // 32 float4 per node
    const float4* gi4 = reinterpret_cast<const float4*>(gi + (size_t)n * 3 * DD);
    const float4* gh4 = reinterpret_cast<const float4*>(gh + (size_t)n * 3 * DD);
    float4 ir = gi4[j],      hr = gh4[j];
    float4 iz = gi4[32 + j], hz = gh4[32 + j];
    float4 in = gi4[64 + j], hn = gh4[64 + j];
    float4 r = sig4(make_float4(ir.x + hr.x, ir.y + hr.y, ir.z + hr.z, ir.w + hr.w));
    float4 z = sig4(make_float4(iz.x + hz.x, iz.y + hz.y, iz.z + hz.z, iz.w + hz.w));
    float4 nn = make_float4(tanhf(in.x + r.x * hn.x), tanhf(in.y + r.y * hn.y),
                            tanhf(in.z + r.z * hn.z), tanhf(in.w + r.w * hn.w));
    float4* h4 = reinterpret_cast<float4*>(h);
    float4 hv = h4[i];
    h4[i] = make_float4((1.f - z.x) * nn.x + z.x * hv.x,
                        (1.f - z.y) * nn.y + z.y * hv.y,
                        (1.f - z.z) * nn.z + z.z * hv.z,
                        (1.f - z.w) * nn.w + z.w * hv.w);
}

// ---------------- readout attn (warp per node) ----------------
__global__ void k_attn(const float* __restrict__ h, const float* __restrict__ wg,
                       const float* __restrict__ bg, float* __restrict__ attn) {
    int warp = (blockIdx.x * blockDim.x + threadIdx.x) >> 5;
    int lane = threadIdx.x & 31;
    if (warp >= NN) return;
    const float4* h4 = reinterpret_cast<const float4*>(h + (size_t)warp * DD);
    const float4* w4 = reinterpret_cast<const float4*>(wg);
    float4 a = h4[lane], b = w4[lane];
    float s = a.x * b.x + a.y * b.y + a.z * b.z + a.w * b.w;
#pragma unroll
    for (int o = 16; o; o >>= 1) s += __shfl_xor_sync(0xFFFFFFFFu, s, o);
    if (lane == 0) attn[warp] = 1.f / (1.f + expf(-(s + bg[0])));
}

// ---------------- launch ----------------
static inline void* symaddr(const void* sym) {
    void* p = nullptr;
    cudaGetSymbolAddress(&p, sym);
    return p;
}

extern "C" void kernel_launch(void* const* d_in, const int* in_sizes, int n_in,
                              void* d_out, int out_size) {
    const int*   node_types = (const int*)d_in[0];
    const int*   edge_src   = (const int*)d_in[1];
    const int*   edge_dst   = (const int*)d_in[2];
    const int*   edge_type  = (const int*)d_in[3];
    const int*   node2graph = (const int*)d_in[4];
    const float* emb   = (const float*)d_in[5];
    const float* W_msg = (const float*)d_in[6];
    const float* b_msg = (const float*)d_in[7];
    const float* W_ih  = (const float*)d_in[8];
    const float* W_hh  = (const float*)d_in[9];
    const float* b_ih  = (const float*)d_in[10];
    const float* b_hh  = (const float*)d_in[11];
    const float* w_gate= (const float*)d_in[12];
    const float* b_gate= (const float*)d_in[13];
    const float* W_g   = (const float*)d_in[14];
    const float* b_g   = (const float*)d_in[15];
    float* out = (float*)d_out;

    float* h      = (float*)symaddr(g_h);
    float* preagg = (float*)symaddr(g_preagg);
    int*   counts = (int*)  symaddr(g_counts);
    float* msgs   = (float*)symaddr(g_msgs);
    float* gi     = (float*)symaddr(g_gi);
    float* gh     = (float*)symaddr(g_gh);
    float* attn   = (float*)symaddr(g_attn);
    int*   hist   = (int*)  symaddr(g_hist);
    int*   cursor = (int*)  symaddr(g_cursor);
    int*   off    = (int*)  symaddr(g_off);
    int*   part   = (int*)  symaddr(g_part);
    int2*  csr    = (int2*) symaddr(g_csr);

    // --- build CSR by src ---
    k_zero2<<<(NN + 255) / 256, 256>>>(hist, cursor, NN);
    k_hist<<<(NE + 255) / 256, 256>>>(edge_src, hist);
    k_scan1<<<NB_SCAN, 256>>>(hist, off, part);
    k_scan2<<<1, 256>>>(part, NB_SCAN);
    k_scan3<<<NB_SCAN, 256>>>(part, off);
    k_scatter<<<(NE + 255) / 256, 256>>>(edge_src, edge_dst, edge_type, off, cursor, csr);

    // --- init h = emb_table[node_types] ---
    k_embed<<<(NN * 32 + 255) / 256, 256>>>(node_types, emb, h);

    const int rowBlocks = (NN + 127) / 128;  // 391

    for (int p = 0; p < NPASS; p++) {
        k_agg<<<(NN * 32 + 255) / 256, 256>>>(h, off, csr, preagg, counts);
        {   // msgs = relu(pre_agg @ W_msg_cat + counts . b_msg)
            dim3 g(rowBlocks, MM / 128);
            k_mma<1, false><<<g, 256>>>(preagg, W_msg, msgs, NN, TT * DD, MM,
                                        nullptr, counts, b_msg, nullptr, nullptr, nullptr);
        }
        {   // gi = msgs @ W_ih^T + b_ih
            dim3 g(rowBlocks, (3 * DD) / 128);
            k_mma<0, true><<<g, 256>>>(msgs, W_ih, gi, NN, MM, 3 * DD,
                                       b_ih, nullptr, nullptr, nullptr, nullptr, nullptr);
        }
        {   // gh = h @ W_hh^T + b_hh
            dim3 g(rowBlocks, (3 * DD) / 128);
            k_mma<0, true><<<g, 256>>>(h, W_hh, gh, NN, DD, 3 * DD,
                                       b_hh, nullptr, nullptr, nullptr, nullptr, nullptr);
        }
        k_gates<<<(NN * DD / 4 + 255) / 256, 256>>>(gi, gh, h);
    }

    // --- output: h first, then gated graph readout ---
    cudaMemcpyAsync(out, h, (size_t)NN * DD * sizeof(float),
                    cudaMemcpyDeviceToDevice);
    float* gout = out + ((size_t)out_size - (size_t)NG * GH);
    cudaMemsetAsync(gout, 0, (size_t)NG * GH * sizeof(float));

    k_attn<<<(NN * 32 + 255) / 256, 256>>>(h, w_gate, b_gate, attn);
    {
        dim3 g(rowBlocks, GH / 128);
        k_mma<2, false><<<g, 256>>>(h, W_g, nullptr, NN, DD, GH,
                                    b_g, nullptr, nullptr, attn, node2graph, gout);
    }
}

// round 6
// speedup vs baseline: 1.5854x; 1.0967x over previous
#include <cuda_runtime.h>
#include <math.h>
#include <stdint.h>

#define NN 50000            // nodes
#define NE 800000           // edges
#define NG 512              // graphs
#define DD 128              // node hidden
#define MM 256              // message hidden
#define TT 4                // edge types
#define NPASS 4
#define GH 256              // graph hidden

// ---------------- scratch (static __device__, no allocations) ----------------
__device__ float g_h[NN * DD];
__device__ float g_preagg[NN * (TT * DD)];    // (N, 512) node-major [t0|t1|t2|t3]
__device__ int   g_counts[NN * TT];
__device__ float g_msgs[NN * MM];
__device__ float g_gi[NN * 3 * DD];
__device__ float g_gh[NN * 3 * DD];
__device__ float g_attn[NN];
__device__ int   g_hist[NN];
__device__ int   g_cursor[NN];
__device__ int   g_off[NN + 1];
__device__ int   g_part[256];
__device__ int2  g_csr[NE];                   // (dst, type) sorted by src
__device__ float g_WmsgT[MM * (TT * DD)];     // (256, 512)  [N,K], tf32-rounded
__device__ float g_WgT[GH * DD];              // (256, 128)  [N,K], tf32-rounded
__device__ float g_WihR[(3 * DD) * MM];       // (384, 256)  rounded copy
__device__ float g_WhhR[(3 * DD) * DD];       // (384, 128)  rounded copy

#define NB_SCAN ((NN + 255) / 256)            // 196

// ---------------- helpers ----------------
__device__ __forceinline__ uint32_t smem_u32(const void* p) {
    uint32_t a;
    asm("{ .reg .u64 t; cvta.to.shared.u64 t, %1; cvt.u32.u64 %0, t; }"
        : "=r"(a) : "l"(p));
    return a;
}

__device__ __forceinline__ float f2tf_f(float x) {
    unsigned r;
    asm("cvt.rna.tf32.f32 %0, %1;" : "=r"(r) : "f"(x));
    return __uint_as_float(r);
}

__device__ __forceinline__ void cp16(uint32_t dst, const void* src, int sz) {
    asm volatile("cp.async.cg.shared.global [%0], [%1], 16, %2;"
                 :: "r"(dst), "l"(src), "r"(sz) : "memory");
}
__device__ __forceinline__ void cp_commit() {
    asm volatile("cp.async.commit_group;" ::: "memory");
}
__device__ __forceinline__ void cp_wait0() {
    asm volatile("cp.async.wait_group 0;" ::: "memory");
}
__device__ __forceinline__ void cp_wait1() {
    asm volatile("cp.async.wait_group 1;" ::: "memory");
}

__device__ __forceinline__ void mma_tf32(float* c, unsigned a0, unsigned a1,
                                         unsigned a2, unsigned a3,
                                         unsigned b0, unsigned b1) {
    asm volatile(
        "mma.sync.aligned.m16n8k8.row.col.f32.tf32.tf32.f32 "
        "{%0,%1,%2,%3}, {%4,%5,%6,%7}, {%8,%9}, {%0,%1,%2,%3};"
        : "+f"(c[0]), "+f"(c[1]), "+f"(c[2]), "+f"(c[3])
        : "r"(a0), "r"(a1), "r"(a2), "r"(a3), "r"(b0), "r"(b1));
}

// ---------------- setup kernels ----------------
__global__ void k_zero2(int* a, int* b, int n) {
    int i = blockIdx.x * blockDim.x + threadIdx.x;
    if (i < n) { a[i] = 0; b[i] = 0; }
}

__global__ void k_hist(const int* __restrict__ src, int* __restrict__ hist) {
    int i = blockIdx.x * blockDim.x + threadIdx.x;
    if (i < NE) atomicAdd(&hist[src[i]], 1);
}

__global__ void k_scan1(const int* __restrict__ hist, int* __restrict__ off,
                        int* __restrict__ part) {
    __shared__ int sh[256];
    int t = threadIdx.x, i = blockIdx.x * 256 + t;
    int v = (i < NN) ? hist[i] : 0;
    sh[t] = v;
    __syncthreads();
#pragma unroll
    for (int o = 1; o < 256; o <<= 1) {
        int x = (t >= o) ? sh[t - o] : 0;
        __syncthreads();
        sh[t] += x;
        __syncthreads();
    }
    if (i < NN) off[i] = sh[t] - v;
    if (t == 255) part[blockIdx.x] = sh[255];
}

__global__ void k_scan2(int* __restrict__ part, int nb) {
    __shared__ int sh[256];
    int t = threadIdx.x;
    int v = (t < nb) ? part[t] : 0;
    sh[t] = v;
    __syncthreads();
#pragma unroll
    for (int o = 1; o < 256; o <<= 1) {
        int x = (t >= o) ? sh[t - o] : 0;
        __syncthreads();
        sh[t] += x;
        __syncthreads();
    }
    if (t < nb) part[t] = sh[t] - v;
}

__global__ void k_scan3(const int* __restrict__ part, int* __restrict__ off) {
    int i = blockIdx.x * 256 + threadIdx.x;
    if (i < NN) off[i] += part[blockIdx.x];
    if (i == 0) off[NN] = NE;
}

__global__ void k_scatter(const int* __restrict__ src, const int* __restrict__ dst,
                          const int* __restrict__ typ,
                          const int* __restrict__ off, int* __restrict__ cursor,
                          int2* __restrict__ csr) {
    int i = blockIdx.x * blockDim.x + threadIdx.x;
    if (i >= NE) return;
    int s = src[i];
    int pos = off[s] + atomicAdd(&cursor[s], 1);
    csr[pos] = make_int2(dst[i], typ[i]);
}

__global__ void k_embed(const int* __restrict__ nt, const float* __restrict__ emb,
                        float* __restrict__ h) {
    int t = blockIdx.x * blockDim.x + threadIdx.x;
    if (t >= NN * 32) return;
    int node = t >> 5, c = t & 31;
    float4 v = reinterpret_cast<const float4*>(emb)[nt[node] * 32 + c];
    v.x = f2tf_f(v.x); v.y = f2tf_f(v.y); v.z = f2tf_f(v.z); v.w = f2tf_f(v.w);
    reinterpret_cast<float4*>(h)[t] = v;
}

// out[n*K + k] = round(in[k*N + n])
__global__ void k_transpose(const float* __restrict__ in, float* __restrict__ out,
                            int K, int N) {
    int i = blockIdx.x * blockDim.x + threadIdx.x;
    if (i >= K * N) return;
    int n = i % N, k = i / N;
    out[n * K + k] = f2tf_f(in[i]);
}

__global__ void k_roundcopy(const float* __restrict__ in, float* __restrict__ out,
                            int n) {
    int i = blockIdx.x * blockDim.x + threadIdx.x;
    if (i < n) out[i] = f2tf_f(in[i]);
}

// ---------------- per-pass: CSR aggregation (warp per node, 8x edge unroll) ----
__device__ __forceinline__ void agg_one(float4 a[4], float c[4],
                                        const float4& v, int ty) {
#pragma unroll
    for (int t = 0; t < 4; t++) {
        float m = (ty == t) ? 1.f : 0.f;
        a[t].x = fmaf(v.x, m, a[t].x);
        a[t].y = fmaf(v.y, m, a[t].y);
        a[t].z = fmaf(v.z, m, a[t].z);
        a[t].w = fmaf(v.w, m, a[t].w);
        c[t] += m;
    }
}

__global__ void k_agg(const float* __restrict__ h, const int* __restrict__ off,
                      const int2* __restrict__ csr,
                      float* __restrict__ preagg, int* __restrict__ counts) {
    int warp = (blockIdx.x * blockDim.x + threadIdx.x) >> 5;
    int lane = threadIdx.x & 31;
    if (warp >= NN) return;
    int beg = off[warp], end = off[warp + 1];
    float4 a[4];
    float c[4] = {0, 0, 0, 0};
#pragma unroll
    for (int t = 0; t < 4; t++) a[t] = make_float4(0, 0, 0, 0);
    const float4* h4 = reinterpret_cast<const float4*>(h);
    int e = beg;
    for (; e + 8 <= end; e += 8) {
        int2 d[8];
        float4 v[8];
#pragma unroll
        for (int q = 0; q < 8; q++) d[q] = csr[e + q];
#pragma unroll
        for (int q = 0; q < 8; q++) v[q] = h4[d[q].x * 32 + lane];
#pragma unroll
        for (int q = 0; q < 8; q++) agg_one(a, c, v[q], d[q].y);
    }
    for (; e + 4 <= end; e += 4) {
        int2 d0 = csr[e], d1 = csr[e + 1], d2 = csr[e + 2], d3 = csr[e + 3];
        float4 v0 = h4[d0.x * 32 + lane];
        float4 v1 = h4[d1.x * 32 + lane];
        float4 v2 = h4[d2.x * 32 + lane];
        float4 v3 = h4[d3.x * 32 + lane];
        agg_one(a, c, v0, d0.y);
        agg_one(a, c, v1, d1.y);
        agg_one(a, c, v2, d2.y);
        agg_one(a, c, v3, d3.y);
    }
    for (; e < end; e++) {
        int2 d = csr[e];
        float4 v = h4[d.x * 32 + lane];
        agg_one(a, c, v, d.y);
    }
    float4* p4 = reinterpret_cast<float4*>(preagg);
    int base = warp * 128;
#pragma unroll
    for (int t = 0; t < 4; t++) {
        float4 r = a[t];
        r.x = f2tf_f(r.x); r.y = f2tf_f(r.y); r.z = f2tf_f(r.z); r.w = f2tf_f(r.w);
        p4[base + t * 32 + lane] = r;
    }
    if (lane == 0) {
#pragma unroll
        for (int t = 0; t < 4; t++) counts[warp * 4 + t] = (int)c[t];
    }
}

// ---------------- TF32 mma.sync GEMM 128x128x32, cp.async double-buffered -----
// A: (Nrows,K) row-major tf32-rounded.  B: (Ncols,K) row-major tf32-rounded.
// MODE 0: C = acc + bias[col]
// MODE 1: C = round(relu(acc + sum_t counts[r][t]*bmsg[t*MM+col]))
// MODE 2: atomicAdd(gout[n2g[r]*GH+col], attn[r]*(acc+bias[col]))
// smem per stage: As 128x36 + Bs 128x36 (n-major, K-minor), 2 stages = 73728 B.

#define STG_WORDS 9216                         // (128*36)*2 per stage
#define GEMM_SMEM (2 * STG_WORDS * 4)

template <int MODE>
__global__ void __launch_bounds__(256)
k_mma(const float* __restrict__ A, const float* __restrict__ B,
      float* __restrict__ C, int Nrows, int K, int Ncols,
      const float* __restrict__ bias,
      const int* __restrict__ counts, const float* __restrict__ bmsg,
      const float* __restrict__ attn, const int* __restrict__ n2g,
      float* __restrict__ gout) {
    extern __shared__ unsigned smu[];
    const uint32_t sbase = smem_u32(smu);

    const int tid = threadIdx.x;
    const int lane = tid & 31;
    const int warp = tid >> 5;
    const int rowBase = blockIdx.x * 128;
    const int colBase = blockIdx.y * 128;
    const int wm = (warp & 3) * 32;
    const int wn = (warp >> 2) * 64;
    const int qrow = lane >> 2;
    const int qcol = lane & 3;

    float acc[2][8][4];
#pragma unroll
    for (int mt = 0; mt < 2; mt++)
#pragma unroll
        for (int nt = 0; nt < 8; nt++)
#pragma unroll
            for (int q = 0; q < 4; q++) acc[mt][nt][q] = 0.f;

    const int cRow = tid >> 3;                 // 0..31 (row step 32, 4 iters)
    const int cK = (tid & 7) * 4;              // 0,4,..28

    auto issue = [&](int t) {
        int st = t & 1;
        uint32_t abase = sbase + st * STG_WORDS * 4;
        uint32_t bbase = abase + 4608 * 4;
        int k0 = t * 32;
#pragma unroll
        for (int u = 0; u < 4; u++) {
            int row = cRow + u * 32;
            const float* src = A + (size_t)(rowBase + row) * K + k0 + cK;
            int sz = (rowBase + row < Nrows) ? 16 : 0;
            cp16(abase + (row * 36 + cK) * 4, src, sz);
        }
#pragma unroll
        for (int u = 0; u < 4; u++) {
            int row = cRow + u * 32;
            const float* src = B + (size_t)(colBase + row) * K + k0 + cK;
            cp16(bbase + (row * 36 + cK) * 4, src, 16);
        }
        cp_commit();
    };

    const int nT = K / 32;
    issue(0);
    for (int t = 0; t < nT; t++) {
        if (t + 1 < nT) { issue(t + 1); cp_wait1(); } else { cp_wait0(); }
        __syncthreads();
        const unsigned* As = smu + (t & 1) * STG_WORDS;
        const unsigned* Bs = As + 4608;
#pragma unroll
        for (int kk = 0; kk < 4; kk++) {
            unsigned af[2][4];
#pragma unroll
            for (int mt = 0; mt < 2; mt++) {
                af[mt][0] = As[(wm + mt * 16 + qrow) * 36 + kk * 8 + qcol];
                af[mt][1] = As[(wm + mt * 16 + qrow + 8) * 36 + kk * 8 + qcol];
                af[mt][2] = As[(wm + mt * 16 + qrow) * 36 + kk * 8 + qcol + 4];
                af[mt][3] = As[(wm + mt * 16 + qrow + 8) * 36 + kk * 8 + qcol + 4];
            }
            unsigned bf[8][2];
#pragma unroll
            for (int nt = 0; nt < 8; nt++) {
                bf[nt][0] = Bs[(wn + nt * 8 + qrow) * 36 + kk * 8 + qcol];
                bf[nt][1] = Bs[(wn + nt * 8 + qrow) * 36 + kk * 8 + qcol + 4];
            }
#pragma unroll
            for (int mt = 0; mt < 2; mt++)
#pragma unroll
                for (int nt = 0; nt < 8; nt++)
                    mma_tf32(acc[mt][nt], af[mt][0], af[mt][1], af[mt][2],
                             af[mt][3], bf[nt][0], bf[nt][1]);
        }
        __syncthreads();
    }

#pragma unroll
    for (int mt = 0; mt < 2; mt++) {
#pragma unroll
        for (int half = 0; half < 2; half++) {
            int r = rowBase + wm + mt * 16 + qrow + half * 8;
            if (r >= Nrows) continue;
            float ct0 = 0, ct1 = 0, ct2 = 0, ct3 = 0, at = 0;
            int gidx = 0;
            if (MODE == 1) {
                ct0 = (float)counts[r * 4 + 0]; ct1 = (float)counts[r * 4 + 1];
                ct2 = (float)counts[r * 4 + 2]; ct3 = (float)counts[r * 4 + 3];
            } else if (MODE == 2) {
                at = attn[r];
                gidx = n2g[r];
            }
#pragma unroll
            for (int nt = 0; nt < 8; nt++) {
#pragma unroll
                for (int e = 0; e < 2; e++) {
                    int c = colBase + wn + nt * 8 + 2 * qcol + e;
                    float v = acc[mt][nt][half * 2 + e];
                    if (MODE == 1) {
                        v += ct0 * bmsg[c] + ct1 * bmsg[MM + c] +
                             ct2 * bmsg[2 * MM + c] + ct3 * bmsg[3 * MM + c];
                        C[(size_t)r * Ncols + c] = f2tf_f(fmaxf(v, 0.f));
                    } else if (MODE == 0) {
                        C[(size_t)r * Ncols + c] = v + bias[c];
                    } else {
                        atomicAdd(&gout[(size_t)gidx * GH + c], at * (v + bias[c]));
                    }
                }
            }
        }
    }
}

// ---------------- GRU gates (float4 vectorized; writes tf32-rounded h) --------
__device__ __forceinline__ float4 sig4(float4 x) {
    return make_float4(1.f / (1.f + __expf(-x.x)), 1.f / (1.f + __expf(-x.y)),
                       1.f / (1.f + __expf(-x.z)), 1.f / (1.f + __expf(-x.w)));
}

__global__ void k_gates(const float* __restrict__ gi, const float* __restrict__ gh,
                        float* __restrict__ h) {
    int i = blockIdx.x * blockDim.x + threadIdx.x;
    if (i >= NN * DD / 4) return;
    int n = i >> 5, j = i & 31;
    const float4* gi4 = reinterpret_cast<const float4*>(gi + (size_t)n * 3 * DD);
    const float4* gh4 = reinterpret_cast<const float4*>(gh + (size_t)n * 3 * DD);
    float4 ir = gi4[j],      hr = gh4[j];
    float4 iz = gi4[32 + j], hz = gh4[32 + j];
    float4 in = gi4[64 + j], hn = gh4[64 + j];
    float4 r = sig4(make_float4(ir.x + hr.x, ir.y + hr.y, ir.z + hr.z, ir.w + hr.w));
    float4 z = sig4(make_float4(iz.x + hz.x, iz.y + hz.y, iz.z + hz.z, iz.w + hz.w));
    float4 nn = make_float4(tanhf(in.x + r.x * hn.x), tanhf(in.y + r.y * hn.y),
                            tanhf(in.z + r.z * hn.z), tanhf(in.w + r.w * hn.w));
    float4* h4 = reinterpret_cast<float4*>(h);
    float4 hv = h4[i];
    h4[i] = make_float4(f2tf_f((1.f - z.x) * nn.x + z.x * hv.x),
                        f2tf_f((1.f - z.y) * nn.y + z.y * hv.y),
                        f2tf_f((1.f - z.z) * nn.z + z.z * hv.z),
                        f2tf_f((1.f - z.w) * nn.w + z.w * hv.w));
}

// ---------------- readout attn (warp per node) ----------------
__global__ void k_attn(const float* __restrict__ h, const float* __restrict__ wg,
                       const float* __restrict__ bg, float* __restrict__ attn) {
    int warp = (blockIdx.x * blockDim.x + threadIdx.x) >> 5;
    int lane = threadIdx.x & 31;
    if (warp >= NN) return;
    const float4* h4 = reinterpret_cast<const float4*>(h + (size_t)warp * DD);
    const float4* w4 = reinterpret_cast<const float4*>(wg);
    float4 a = h4[lane], b = w4[lane];
    float s = a.x * b.x + a.y * b.y + a.z * b.z + a.w * b.w;
#pragma unroll
    for (int o = 16; o; o >>= 1) s += __shfl_xor_sync(0xFFFFFFFFu, s, o);
    if (lane == 0) attn[warp] = 1.f / (1.f + expf(-(s + bg[0])));
}

// ---------------- launch ----------------
static inline void* symaddr(const void* sym) {
    void* p = nullptr;
    cudaGetSymbolAddress(&p, sym);
    return p;
}

extern "C" void kernel_launch(void* const* d_in, const int* in_sizes, int n_in,
                              void* d_out, int out_size) {
    const int*   node_types = (const int*)d_in[0];
    const int*   edge_src   = (const int*)d_in[1];
    const int*   edge_dst   = (const int*)d_in[2];
    const int*   edge_type  = (const int*)d_in[3];
    const int*   node2graph = (const int*)d_in[4];
    const float* emb   = (const float*)d_in[5];
    const float* W_msg = (const float*)d_in[6];   // (512, 256)
    const float* b_msg = (const float*)d_in[7];
    const float* W_ih  = (const float*)d_in[8];   // (384, 256) = [N,K]
    const float* W_hh  = (const float*)d_in[9];   // (384, 128) = [N,K]
    const float* b_ih  = (const float*)d_in[10];
    const float* b_hh  = (const float*)d_in[11];
    const float* w_gate= (const float*)d_in[12];
    const float* b_gate= (const float*)d_in[13];
    const float* W_g   = (const float*)d_in[14];  // (128, 256)
    const float* b_g   = (const float*)d_in[15];
    float* out = (float*)d_out;

    float* h      = (float*)symaddr(g_h);
    float* preagg = (float*)symaddr(g_preagg);
    int*   counts = (int*)  symaddr(g_counts);
    float* msgs   = (float*)symaddr(g_msgs);
    float* gi     = (float*)symaddr(g_gi);
    float* gh     = (float*)symaddr(g_gh);
    float* attn   = (float*)symaddr(g_attn);
    int*   hist   = (int*)  symaddr(g_hist);
    int*   cursor = (int*)  symaddr(g_cursor);
    int*   off    = (int*)  symaddr(g_off);
    int*   part   = (int*)  symaddr(g_part);
    int2*  csr    = (int2*) symaddr(g_csr);
    float* WmsgT  = (float*)symaddr(g_WmsgT);
    float* WgT    = (float*)symaddr(g_WgT);
    float* WihR   = (float*)symaddr(g_WihR);
    float* WhhR   = (float*)symaddr(g_WhhR);

    cudaFuncSetAttribute(k_mma<0>, cudaFuncAttributeMaxDynamicSharedMemorySize, GEMM_SMEM);
    cudaFuncSetAttribute(k_mma<1>, cudaFuncAttributeMaxDynamicSharedMemorySize, GEMM_SMEM);
    cudaFuncSetAttribute(k_mma<2>, cudaFuncAttributeMaxDynamicSharedMemorySize, GEMM_SMEM);

    // --- build CSR by src ---
    k_zero2<<<(NN + 255) / 256, 256>>>(hist, cursor, NN);
    k_hist<<<(NE + 255) / 256, 256>>>(edge_src, hist);
    k_scan1<<<NB_SCAN, 256>>>(hist, off, part);
    k_scan2<<<1, 256>>>(part, NB_SCAN);
    k_scan3<<<NB_SCAN, 256>>>(part, off);
    k_scatter<<<(NE + 255) / 256, 256>>>(edge_src, edge_dst, edge_type, off, cursor, csr);

    // --- weight prep: [N,K] layout, tf32-rounded ---
    k_transpose<<<(512 * 256 + 255) / 256, 256>>>(W_msg, WmsgT, 512, 256);
    k_transpose<<<(128 * 256 + 255) / 256, 256>>>(W_g, WgT, 128, 256);
    k_roundcopy<<<(384 * 256 + 255) / 256, 256>>>(W_ih, WihR, 384 * 256);
    k_roundcopy<<<(384 * 128 + 255) / 256, 256>>>(W_hh, WhhR, 384 * 128);

    // --- init h = round(emb_table[node_types]) ---
    k_embed<<<(NN * 32 + 255) / 256, 256>>>(node_types, emb, h);

    const int rowBlocks = (NN + 127) / 128;  // 391

    for (int p = 0; p < NPASS; p++) {
        k_agg<<<(NN * 32 + 255) / 256, 256>>>(h, off, csr, preagg, counts);
        {   // msgs = relu(pre_agg @ W_msg_cat + counts . b_msg)   K=512
            dim3 g(rowBlocks, 2);
            k_mma<1><<<g, 256, GEMM_SMEM>>>(preagg, WmsgT, msgs, NN, TT * DD, MM,
                                            nullptr, counts, b_msg, nullptr, nullptr, nullptr);
        }
        {   // gi = msgs @ W_ih^T + b_ih   K=256
            dim3 g(rowBlocks, 3);
            k_mma<0><<<g, 256, GEMM_SMEM>>>(msgs, WihR, gi, NN, MM, 3 * DD,
                                            b_ih, nullptr, nullptr, nullptr, nullptr, nullptr);
        }
        {   // gh = h @ W_hh^T + b_hh   K=128
            dim3 g(rowBlocks, 3);
            k_mma<0><<<g, 256, GEMM_SMEM>>>(h, WhhR, gh, NN, DD, 3 * DD,
                                            b_hh, nullptr, nullptr, nullptr, nullptr, nullptr);
        }
        k_gates<<<(NN * DD / 4 + 255) / 256, 256>>>(gi, gh, h);
    }

    // --- output: h first, then gated graph readout ---
    cudaMemcpyAsync(out, h, (size_t)NN * DD * sizeof(float),
                    cudaMemcpyDeviceToDevice);
    float* gout = out + ((size_t)out_size - (size_t)NG * GH);
    cudaMemsetAsync(gout, 0, (size_t)NG * GH * sizeof(float));

    k_attn<<<(NN * 32 + 255) / 256, 256>>>(h, w_gate, b_gate, attn);
    {   // K=128
        dim3 g(rowBlocks, 2);
        k_mma<2><<<g, 256, GEMM_SMEM>>>(h, WgT, nullptr, NN, DD, GH,
                                        b_g, nullptr, nullptr, attn, node2graph, gout);
    }
}

// round 7
// speedup vs baseline: 1.9356x; 1.2209x over previous
#include <cuda_runtime.h>
#include <cuda_fp16.h>
#include <math.h>
#include <stdint.h>

#define NN 50000            // nodes
#define NE 800000           // edges
#define NG 512              // graphs
#define DD 128              // node hidden
#define MM 256              // message hidden
#define TT 4                // edge types
#define NPASS 4
#define GH 256              // graph hidden

// ---------------- scratch (static __device__, no allocations) ----------------
__device__ float  g_hf[NN * DD];              // fp32 node state (GRU/attn/output)
__device__ __half g_h16[NN * DD];             // fp16 mirror (GEMM/agg operand)
__device__ __half g_preagg[NN * (TT * DD)];   // (N, 512) fp16
__device__ int    g_counts[NN * TT];
__device__ __half g_msgs[NN * MM];            // fp16
__device__ float  g_gi[NN * 3 * DD];
__device__ float  g_gh[NN * 3 * DD];
__device__ float  g_attn[NN];
__device__ int    g_hist[NN];
__device__ int    g_cursor[NN];
__device__ int    g_off[NN + 1];
__device__ int    g_part[256];
__device__ int2   g_csr[NE];
__device__ __half g_WmsgT[MM * (TT * DD)];    // (256, 512) [N,K] fp16
__device__ __half g_WgT[GH * DD];             // (256, 128) [N,K] fp16
__device__ __half g_WihR[(3 * DD) * MM];      // (384, 256) fp16
__device__ __half g_WhhR[(3 * DD) * DD];      // (384, 128) fp16

#define NB_SCAN ((NN + 255) / 256)            // 196

// ---------------- helpers ----------------
__device__ __forceinline__ uint32_t smem_u32(const void* p) {
    uint32_t a;
    asm("{ .reg .u64 t; cvta.to.shared.u64 t, %1; cvt.u32.u64 %0, t; }"
        : "=r"(a) : "l"(p));
    return a;
}

__device__ __forceinline__ void cp16(uint32_t dst, const void* src, int sz) {
    asm volatile("cp.async.cg.shared.global [%0], [%1], 16, %2;"
                 :: "r"(dst), "l"(src), "r"(sz) : "memory");
}
__device__ __forceinline__ void cp_commit() {
    asm volatile("cp.async.commit_group;" ::: "memory");
}
__device__ __forceinline__ void cp_wait0() {
    asm volatile("cp.async.wait_group 0;" ::: "memory");
}
__device__ __forceinline__ void cp_wait1() {
    asm volatile("cp.async.wait_group 1;" ::: "memory");
}

__device__ __forceinline__ void mma_f16(float* c, unsigned a0, unsigned a1,
                                        unsigned a2, unsigned a3,
                                        unsigned b0, unsigned b1) {
    asm volatile(
        "mma.sync.aligned.m16n8k16.row.col.f32.f16.f16.f32 "
        "{%0,%1,%2,%3}, {%4,%5,%6,%7}, {%8,%9}, {%0,%1,%2,%3};"
        : "+f"(c[0]), "+f"(c[1]), "+f"(c[2]), "+f"(c[3])
        : "r"(a0), "r"(a1), "r"(a2), "r"(a3), "r"(b0), "r"(b1));
}

__device__ __forceinline__ unsigned pack2(float x, float y) {
    __half2 p = __floats2half2_rn(x, y);
    return *reinterpret_cast<unsigned*>(&p);
}

// ---------------- setup kernels ----------------
__global__ void k_zero2(int* a, int* b, int n) {
    int i = blockIdx.x * blockDim.x + threadIdx.x;
    if (i < n) { a[i] = 0; b[i] = 0; }
}

__global__ void k_hist(const int* __restrict__ src, int* __restrict__ hist) {
    int i = blockIdx.x * blockDim.x + threadIdx.x;
    if (i < NE) atomicAdd(&hist[src[i]], 1);
}

__global__ void k_scan1(const int* __restrict__ hist, int* __restrict__ off,
                        int* __restrict__ part) {
    __shared__ int sh[256];
    int t = threadIdx.x, i = blockIdx.x * 256 + t;
    int v = (i < NN) ? hist[i] : 0;
    sh[t] = v;
    __syncthreads();
#pragma unroll
    for (int o = 1; o < 256; o <<= 1) {
        int x = (t >= o) ? sh[t - o] : 0;
        __syncthreads();
        sh[t] += x;
        __syncthreads();
    }
    if (i < NN) off[i] = sh[t] - v;
    if (t == 255) part[blockIdx.x] = sh[255];
}

__global__ void k_scan2(int* __restrict__ part, int nb) {
    __shared__ int sh[256];
    int t = threadIdx.x;
    int v = (t < nb) ? part[t] : 0;
    sh[t] = v;
    __syncthreads();
#pragma unroll
    for (int o = 1; o < 256; o <<= 1) {
        int x = (t >= o) ? sh[t - o] : 0;
        __syncthreads();
        sh[t] += x;
        __syncthreads();
    }
    if (t < nb) part[t] = sh[t] - v;
}

__global__ void k_scan3(const int* __restrict__ part, int* __restrict__ off) {
    int i = blockIdx.x * 256 + threadIdx.x;
    if (i < NN) off[i] += part[blockIdx.x];
    if (i == 0) off[NN] = NE;
}

__global__ void k_scatter(const int* __restrict__ src, const int* __restrict__ dst,
                          const int* __restrict__ typ,
                          const int* __restrict__ off, int* __restrict__ cursor,
                          int2* __restrict__ csr) {
    int i = blockIdx.x * blockDim.x + threadIdx.x;
    if (i >= NE) return;
    int s = src[i];
    int pos = off[s] + atomicAdd(&cursor[s], 1);
    csr[pos] = make_int2(dst[i], typ[i]);
}

// h (fp32 + fp16) = emb_table[node_types]
__global__ void k_embed(const int* __restrict__ nt, const float* __restrict__ emb,
                        float* __restrict__ hf, __half* __restrict__ h16) {
    int t = blockIdx.x * blockDim.x + threadIdx.x;
    if (t >= NN * 32) return;
    int node = t >> 5, c = t & 31;
    float4 v = reinterpret_cast<const float4*>(emb)[nt[node] * 32 + c];
    reinterpret_cast<float4*>(hf)[t] = v;
    uint2 u;
    u.x = pack2(v.x, v.y);
    u.y = pack2(v.z, v.w);
    reinterpret_cast<uint2*>(h16)[t] = u;
}

// out[n*K + k] = half(in[k*N + n])
__global__ void k_transpose(const float* __restrict__ in, __half* __restrict__ out,
                            int K, int N) {
    int i = blockIdx.x * blockDim.x + threadIdx.x;
    if (i >= K * N) return;
    int n = i % N, k = i / N;
    out[n * K + k] = __float2half_rn(in[i]);
}

__global__ void k_roundcopy(const float* __restrict__ in, __half* __restrict__ out,
                            int n) {
    int i = blockIdx.x * blockDim.x + threadIdx.x;
    if (i < n) out[i] = __float2half_rn(in[i]);
}

// ---------------- per-pass: CSR aggregation (warp per node, fp16 gather) ------
// lane handles 4 channels (uint2 = 4 fp16); accumulate fp32.
__device__ __forceinline__ void agg_one(float4 a[4], float c[4],
                                        const uint2& u, int ty) {
    float2 lo = __half22float2(*reinterpret_cast<const __half2*>(&u.x));
    float2 hi = __half22float2(*reinterpret_cast<const __half2*>(&u.y));
#pragma unroll
    for (int t = 0; t < 4; t++) {
        float m = (ty == t) ? 1.f : 0.f;
        a[t].x = fmaf(lo.x, m, a[t].x);
        a[t].y = fmaf(lo.y, m, a[t].y);
        a[t].z = fmaf(hi.x, m, a[t].z);
        a[t].w = fmaf(hi.y, m, a[t].w);
        c[t] += m;
    }
}

__global__ void k_agg(const __half* __restrict__ h, const int* __restrict__ off,
                      const int2* __restrict__ csr,
                      __half* __restrict__ preagg, int* __restrict__ counts) {
    int warp = (blockIdx.x * blockDim.x + threadIdx.x) >> 5;
    int lane = threadIdx.x & 31;
    if (warp >= NN) return;
    int beg = off[warp], end = off[warp + 1];
    float4 a[4];
    float c[4] = {0, 0, 0, 0};
#pragma unroll
    for (int t = 0; t < 4; t++) a[t] = make_float4(0, 0, 0, 0);
    const uint2* h2 = reinterpret_cast<const uint2*>(h);
    int e = beg;
    for (; e + 8 <= end; e += 8) {
        int2 d[8];
        uint2 v[8];
#pragma unroll
        for (int q = 0; q < 8; q++) d[q] = csr[e + q];
#pragma unroll
        for (int q = 0; q < 8; q++) v[q] = h2[d[q].x * 32 + lane];
#pragma unroll
        for (int q = 0; q < 8; q++) agg_one(a, c, v[q], d[q].y);
    }
    for (; e < end; e++) {
        int2 d = csr[e];
        uint2 v = h2[d.x * 32 + lane];
        agg_one(a, c, v, d.y);
    }
    uint2* p2 = reinterpret_cast<uint2*>(preagg);
    int base = warp * 128;                     // 512 halfs = 128 uint2 per node
#pragma unroll
    for (int t = 0; t < 4; t++) {
        uint2 u;
        u.x = pack2(a[t].x, a[t].y);
        u.y = pack2(a[t].z, a[t].w);
        p2[base + t * 32 + lane] = u;
    }
    if (lane == 0) {
#pragma unroll
        for (int t = 0; t < 4; t++) counts[warp * 4 + t] = (int)c[t];
    }
}

// ---------------- FP16 mma.sync GEMM 128x128x32, cp.async double-buffered -----
// A: (Nrows,K) fp16 row-major.  B: (Ncols,K) fp16 row-major.
// smem row: 32 fp16 = 16 words + 4 pad = 20 words (stride-20: conflict-free).
// MODE 0: Cf = acc + bias[col]                         (fp32 out)
// MODE 1: Ch = half(relu(acc + counts.bmsg))           (fp16 out)
// MODE 2: atomicAdd(gout[n2g[r]*GH+col], attn[r]*(acc+bias[col]))

#define STG_WORDS 5120                          // (128*20)*2 words per stage
#define GEMM_SMEM (2 * STG_WORDS * 4)           // 40 KB

template <int MODE>
__global__ void __launch_bounds__(256)
k_mma(const __half* __restrict__ A, const __half* __restrict__ B,
      void* __restrict__ Cv, int Nrows, int K, int Ncols,
      const float* __restrict__ bias,
      const int* __restrict__ counts, const float* __restrict__ bmsg,
      const float* __restrict__ attn, const int* __restrict__ n2g,
      float* __restrict__ gout) {
    extern __shared__ unsigned smu[];
    const uint32_t sbase = smem_u32(smu);

    const int tid = threadIdx.x;
    const int lane = tid & 31;
    const int warp = tid >> 5;
    const int rowBase = blockIdx.x * 128;
    const int colBase = blockIdx.y * 128;
    const int wm = (warp & 3) * 32;
    const int wn = (warp >> 2) * 64;
    const int qrow = lane >> 2;
    const int qcol = lane & 3;

    float acc[2][8][4];
#pragma unroll
    for (int mt = 0; mt < 2; mt++)
#pragma unroll
        for (int nt = 0; nt < 8; nt++)
#pragma unroll
            for (int q = 0; q < 4; q++) acc[mt][nt][q] = 0.f;

    const int cRow = tid >> 1;                 // 0..127
    const int cC0 = (tid & 1) * 2;             // chunk 0/2

    auto issue = [&](int t) {
        int st = t & 1;
        uint32_t abase = sbase + st * STG_WORDS * 4;
        uint32_t bbase = abase + 2560 * 4;
        int k0 = t * 32;
#pragma unroll
        for (int u = 0; u < 2; u++) {
            int ch = cC0 + u;                  // 16B chunk = 8 halfs
            const __half* srcA = A + (size_t)(rowBase + cRow) * K + k0 + ch * 8;
            int sz = (rowBase + cRow < Nrows) ? 16 : 0;
            cp16(abase + cRow * 80 + ch * 16, srcA, sz);
            const __half* srcB = B + (size_t)(colBase + cRow) * K + k0 + ch * 8;
            cp16(bbase + cRow * 80 + ch * 16, srcB, 16);
        }
        cp_commit();
    };

    const int nT = K / 32;
    issue(0);
    for (int t = 0; t < nT; t++) {
        if (t + 1 < nT) { issue(t + 1); cp_wait1(); } else { cp_wait0(); }
        __syncthreads();
        const unsigned* As = smu + (t & 1) * STG_WORDS;
        const unsigned* Bs = As + 2560;
#pragma unroll
        for (int kk = 0; kk < 2; kk++) {       // 16 k per step
            unsigned af[2][4];
#pragma unroll
            for (int mt = 0; mt < 2; mt++) {
                int r0 = wm + mt * 16 + qrow;
                af[mt][0] = As[r0 * 20 + kk * 8 + qcol];
                af[mt][1] = As[(r0 + 8) * 20 + kk * 8 + qcol];
                af[mt][2] = As[r0 * 20 + kk * 8 + qcol + 4];
                af[mt][3] = As[(r0 + 8) * 20 + kk * 8 + qcol + 4];
            }
            unsigned bf[8][2];
#pragma unroll
            for (int nt = 0; nt < 8; nt++) {
                int n0 = wn + nt * 8 + qrow;
                bf[nt][0] = Bs[n0 * 20 + kk * 8 + qcol];
                bf[nt][1] = Bs[n0 * 20 + kk * 8 + qcol + 4];
            }
#pragma unroll
            for (int mt = 0; mt < 2; mt++)
#pragma unroll
                for (int nt = 0; nt < 8; nt++)
                    mma_f16(acc[mt][nt], af[mt][0], af[mt][1], af[mt][2],
                            af[mt][3], bf[nt][0], bf[nt][1]);
        }
        __syncthreads();
    }

#pragma unroll
    for (int mt = 0; mt < 2; mt++) {
#pragma unroll
        for (int half = 0; half < 2; half++) {
            int r = rowBase + wm + mt * 16 + qrow + half * 8;
            if (r >= Nrows) continue;
            float ct0 = 0, ct1 = 0, ct2 = 0, ct3 = 0, at = 0;
            int gidx = 0;
            if (MODE == 1) {
                ct0 = (float)counts[r * 4 + 0]; ct1 = (float)counts[r * 4 + 1];
                ct2 = (float)counts[r * 4 + 2]; ct3 = (float)counts[r * 4 + 3];
            } else if (MODE == 2) {
                at = attn[r];
                gidx = n2g[r];
            }
#pragma unroll
            for (int nt = 0; nt < 8; nt++) {
                int c0 = colBase + wn + nt * 8 + 2 * qcol;
                float v0 = acc[mt][nt][half * 2 + 0];
                float v1 = acc[mt][nt][half * 2 + 1];
                if (MODE == 1) {
                    __half* C = (__half*)Cv;
                    float w0 = v0 + ct0 * bmsg[c0] + ct1 * bmsg[MM + c0] +
                               ct2 * bmsg[2 * MM + c0] + ct3 * bmsg[3 * MM + c0];
                    float w1 = v1 + ct0 * bmsg[c0 + 1] + ct1 * bmsg[MM + c0 + 1] +
                               ct2 * bmsg[2 * MM + c0 + 1] + ct3 * bmsg[3 * MM + c0 + 1];
                    __half2 p = __floats2half2_rn(fmaxf(w0, 0.f), fmaxf(w1, 0.f));
                    *reinterpret_cast<__half2*>(C + (size_t)r * Ncols + c0) = p;
                } else if (MODE == 0) {
                    float* C = (float*)Cv;
                    C[(size_t)r * Ncols + c0] = v0 + bias[c0];
                    C[(size_t)r * Ncols + c0 + 1] = v1 + bias[c0 + 1];
                } else {
                    atomicAdd(&gout[(size_t)gidx * GH + c0], at * (v0 + bias[c0]));
                    atomicAdd(&gout[(size_t)gidx * GH + c0 + 1], at * (v1 + bias[c0 + 1]));
                }
            }
        }
    }
}

// ---------------- GRU gates: fp32 state + fp16 mirror ----------------
__device__ __forceinline__ float4 sig4(float4 x) {
    return make_float4(1.f / (1.f + __expf(-x.x)), 1.f / (1.f + __expf(-x.y)),
                       1.f / (1.f + __expf(-x.z)), 1.f / (1.f + __expf(-x.w)));
}

__global__ void k_gates(const float* __restrict__ gi, const float* __restrict__ gh,
                        float* __restrict__ hf, __half* __restrict__ h16) {
    int i = blockIdx.x * blockDim.x + threadIdx.x;
    if (i >= NN * DD / 4) return;
    int n = i >> 5, j = i & 31;
    const float4* gi4 = reinterpret_cast<const float4*>(gi + (size_t)n * 3 * DD);
    const float4* gh4 = reinterpret_cast<const float4*>(gh + (size_t)n * 3 * DD);
    float4 ir = gi4[j],      hr = gh4[j];
    float4 iz = gi4[32 + j], hz = gh4[32 + j];
    float4 in = gi4[64 + j], hn = gh4[64 + j];
    float4 r = sig4(make_float4(ir.x + hr.x, ir.y + hr.y, ir.z + hr.z, ir.w + hr.w));
    float4 z = sig4(make_float4(iz.x + hz.x, iz.y + hz.y, iz.z + hz.z, iz.w + hz.w));
    float4 nv = make_float4(tanhf(in.x + r.x * hn.x), tanhf(in.y + r.y * hn.y),
                            tanhf(in.z + r.z * hn.z), tanhf(in.w + r.w * hn.w));
    float4* h4 = reinterpret_cast<float4*>(hf);
    float4 hv = h4[i];
    float4 o = make_float4((1.f - z.x) * nv.x + z.x * hv.x,
                           (1.f - z.y) * nv.y + z.y * hv.y,
                           (1.f - z.z) * nv.z + z.z * hv.z,
                           (1.f - z.w) * nv.w + z.w * hv.w);
    h4[i] = o;
    uint2 u;
    u.x = pack2(o.x, o.y);
    u.y = pack2(o.z, o.w);
    reinterpret_cast<uint2*>(h16)[i] = u;
}

// ---------------- readout attn (warp per node, fp32 h) ----------------
__global__ void k_attn(const float* __restrict__ h, const float* __restrict__ wg,
                       const float* __restrict__ bg, float* __restrict__ attn) {
    int warp = (blockIdx.x * blockDim.x + threadIdx.x) >> 5;
    int lane = threadIdx.x & 31;
    if (warp >= NN) return;
    const float4* h4 = reinterpret_cast<const float4*>(h + (size_t)warp * DD);
    const float4* w4 = reinterpret_cast<const float4*>(wg);
    float4 a = h4[lane], b = w4[lane];
    float s = a.x * b.x + a.y * b.y + a.z * b.z + a.w * b.w;
#pragma unroll
    for (int o = 16; o; o >>= 1) s += __shfl_xor_sync(0xFFFFFFFFu, s, o);
    if (lane == 0) attn[warp] = 1.f / (1.f + expf(-(s + bg[0])));
}

// ---------------- launch ----------------
static inline void* symaddr(const void* sym) {
    void* p = nullptr;
    cudaGetSymbolAddress(&p, sym);
    return p;
}

extern "C" void kernel_launch(void* const* d_in, const int* in_sizes, int n_in,
                              void* d_out, int out_size) {
    const int*   node_types = (const int*)d_in[0];
    const int*   edge_src   = (const int*)d_in[1];
    const int*   edge_dst   = (const int*)d_in[2];
    const int*   edge_type  = (const int*)d_in[3];
    const int*   node2graph = (const int*)d_in[4];
    const float* emb   = (const float*)d_in[5];
    const float* W_msg = (const float*)d_in[6];
    const float* b_msg = (const float*)d_in[7];
    const float* W_ih  = (const float*)d_in[8];
    const float* W_hh  = (const float*)d_in[9];
    const float* b_ih  = (const float*)d_in[10];
    const float* b_hh  = (const float*)d_in[11];
    const float* w_gate= (const float*)d_in[12];
    const float* b_gate= (const float*)d_in[13];
    const float* W_g   = (const float*)d_in[14];
    const float* b_g   = (const float*)d_in[15];
    float* out = (float*)d_out;

    float*  hf     = (float*) symaddr(g_hf);
    __half* h16    = (__half*)symaddr(g_h16);
    __half* preagg = (__half*)symaddr(g_preagg);
    int*    counts = (int*)   symaddr(g_counts);
    __half* msgs   = (__half*)symaddr(g_msgs);
    float*  gi     = (float*) symaddr(g_gi);
    float*  gh     = (float*) symaddr(g_gh);
    float*  attn   = (float*) symaddr(g_attn);
    int*    hist   = (int*)   symaddr(g_hist);
    int*    cursor = (int*)   symaddr(g_cursor);
    int*    off    = (int*)   symaddr(g_off);
    int*    part   = (int*)   symaddr(g_part);
    int2*   csr    = (int2*)  symaddr(g_csr);
    __half* WmsgT  = (__half*)symaddr(g_WmsgT);
    __half* WgT    = (__half*)symaddr(g_WgT);
    __half* WihR   = (__half*)symaddr(g_WihR);
    __half* WhhR   = (__half*)symaddr(g_WhhR);

    cudaFuncSetAttribute(k_mma<0>, cudaFuncAttributeMaxDynamicSharedMemorySize, GEMM_SMEM);
    cudaFuncSetAttribute(k_mma<1>, cudaFuncAttributeMaxDynamicSharedMemorySize, GEMM_SMEM);
    cudaFuncSetAttribute(k_mma<2>, cudaFuncAttributeMaxDynamicSharedMemorySize, GEMM_SMEM);

    // --- build CSR by src ---
    k_zero2<<<(NN + 255) / 256, 256>>>(hist, cursor, NN);
    k_hist<<<(NE + 255) / 256, 256>>>(edge_src, hist);
    k_scan1<<<NB_SCAN, 256>>>(hist, off, part);
    k_scan2<<<1, 256>>>(part, NB_SCAN);
    k_scan3<<<NB_SCAN, 256>>>(part, off);
    k_scatter<<<(NE + 255) / 256, 256>>>(edge_src, edge_dst, edge_type, off, cursor, csr);

    // --- weight prep: [N,K] fp16 ---
    k_transpose<<<(512 * 256 + 255) / 256, 256>>>(W_msg, WmsgT, 512, 256);
    k_transpose<<<(128 * 256 + 255) / 256, 256>>>(W_g, WgT, 128, 256);
    k_roundcopy<<<(384 * 256 + 255) / 256, 256>>>(W_ih, WihR, 384 * 256);
    k_roundcopy<<<(384 * 128 + 255) / 256, 256>>>(W_hh, WhhR, 384 * 128);

    // --- init h ---
    k_embed<<<(NN * 32 + 255) / 256, 256>>>(node_types, emb, hf, h16);

    const int rowBlocks = (NN + 127) / 128;  // 391

    for (int p = 0; p < NPASS; p++) {
        k_agg<<<(NN * 32 + 255) / 256, 256>>>(h16, off, csr, preagg, counts);
        {   // msgs = relu(pre_agg @ W_msg_cat + counts . b_msg)   K=512
            dim3 g(rowBlocks, 2);
            k_mma<1><<<g, 256, GEMM_SMEM>>>(preagg, WmsgT, msgs, NN, TT * DD, MM,
                                            nullptr, counts, b_msg, nullptr, nullptr, nullptr);
        }
        {   // gi = msgs @ W_ih^T + b_ih   K=256
            dim3 g(rowBlocks, 3);
            k_mma<0><<<g, 256, GEMM_SMEM>>>(msgs, WihR, gi, NN, MM, 3 * DD,
                                            b_ih, nullptr, nullptr, nullptr, nullptr, nullptr);
        }
        {   // gh = h @ W_hh^T + b_hh   K=128
            dim3 g(rowBlocks, 3);
            k_mma<0><<<g, 256, GEMM_SMEM>>>(h16, WhhR, gh, NN, DD, 3 * DD,
                                            b_hh, nullptr, nullptr, nullptr, nullptr, nullptr);
        }
        k_gates<<<(NN * DD / 4 + 255) / 256, 256>>>(gi, gh, hf, h16);
    }

    // --- output: h (fp32) first, then gated graph readout ---
    cudaMemcpyAsync(out, hf, (size_t)NN * DD * sizeof(float),
                    cudaMemcpyDeviceToDevice);
    float* gout = out + ((size_t)out_size - (size_t)NG * GH);
    cudaMemsetAsync(gout, 0, (size_t)NG * GH * sizeof(float));

    k_attn<<<(NN * 32 + 255) / 256, 256>>>(hf, w_gate, b_gate, attn);
    {   // K=128
        dim3 g(rowBlocks, 2);
        k_mma<2><<<g, 256, GEMM_SMEM>>>(h16, WgT, nullptr, NN, DD, GH,
                                        b_g, nullptr, nullptr, attn, node2graph, gout);
    }
}